// round 17
// baseline (speedup 1.0000x reference)
#include <cuda_runtime.h>

// labels [16, 8, 512, 512] float32
#define HH 512
#define WW 512
#define NIMG 128
#define ROWS 32                       // output rows per band
#define BANDS (HH / ROWS)             // 16
#define NBLOCKS (NIMG * BANDS)        // 2048 CTAs
#define NTHR 64                       // 2 warps; 8 cols/thread over full 512 width
#define NSTG 4                        // SMEM ring stages (32 KB) -> 6 CTAs/SM
#define SROWS 4                       // rows per stage
#define TSTAGES 9                     // rows t=0..35 issued, t<=t_stop used
#define INV_N (1.0f / 33554432.0f)

__device__ __align__(16) float g_partials[NBLOCKS];
__device__ unsigned int g_counter = 0;

__device__ __forceinline__ void cp16(unsigned sa, const float* g) {
    asm volatile("cp.async.cg.shared.global [%0], [%1], 16;" :: "r"(sa), "l"(g));
}
__device__ __forceinline__ void cpcommit() {
    asm volatile("cp.async.commit_group;" ::: "memory");
}
__device__ __forceinline__ void cpwait() {                 // <= NSTG-2 groups pending
    asm volatile("cp.async.wait_group 2;" ::: "memory");
}

__global__ __launch_bounds__(NTHR) void open_mse_kernel(const float* __restrict__ x,
                                                        float* __restrict__ out) {
    __shared__ float smem[NSTG * SROWS][WW];               // 32 KB
    const int tid  = threadIdx.x;
    const int wid  = tid >> 5;
    const int lane = tid & 31;
    const int band = blockIdx.x & (BANDS - 1);
    const int img  = blockIdx.x >> 4;                      // BANDS = 16
    const int r0   = band * ROWS;
    const bool bottom = (r0 + ROWS == HH);
    const int t_stop  = bottom ? ROWS : (ROWS + 1);        // last erosion-row index t

    const float* base = x + (size_t)img * (HH * WW);
    const int c  = tid * 8;
    const int cL = (c == 0) ? 0 : (c - 1);                 // erosion reflect at col 0
    const int cR = (c + 8 < WW) ? (c + 8) : (WW - 2);      // rm[8]=rm[7] at right edge

    // ---- async producer: stage s = rows t in [4s,4s+3], global row clamp(r0-1+t) ----
    auto issue = [&](int s) {
        #pragma unroll
        for (int k = 0; k < SROWS; ++k) {
            int t = s * SROWS + k;
            int g = r0 - 1 + t;
            g = g < 0 ? 0 : (g > HH - 1 ? HH - 1 : g);
            const float* src = base + (size_t)g * WW + c;
            unsigned sa = (unsigned)__cvta_generic_to_shared(&smem[(s % NSTG) * SROWS + k][c]);
            cp16(sa, src);
            cp16(sa + 16, src + 4);
        }
        cpcommit();
    };

    #pragma unroll
    for (int s = 0; s < NSTG - 1; ++s) issue(s);           // prefetch stages 0..2

    float rm_prev[9], er_prev[9], x_prev[8];
    float acc = 0.f;

    // fully local per-row update: 8 output cols from a 10-float SMEM window
    auto full_row = [&](const float* row) {
        float4 v0 = *(const float4*)(row + c);
        float4 v1 = *(const float4*)(row + c + 4);
        float a[8] = {v0.x, v0.y, v0.z, v0.w, v1.x, v1.y, v1.z, v1.w};
        float xm1 = row[cL], x8r = row[cR];
        float rm[9];
        rm[0] = fminf(xm1, a[0]);
        #pragma unroll
        for (int j = 1; j < 8; ++j) rm[j] = fminf(a[j - 1], a[j]);
        rm[8] = fminf(a[7], x8r);
        float er[9], vm[9];
        #pragma unroll
        for (int j = 0; j < 9; ++j) {
            er[j] = fminf(rm_prev[j], rm[j]);
            vm[j] = fmaxf(er_prev[j], er[j]);
        }
        #pragma unroll
        for (int j = 0; j < 8; ++j) {
            float op = fmaxf(vm[j], vm[j + 1]);
            float d  = x_prev[j] - op;
            acc += d * d;
        }
        #pragma unroll
        for (int j = 0; j < 9; ++j) { rm_prev[j] = rm[j]; er_prev[j] = er[j]; }
        #pragma unroll
        for (int j = 0; j < 8; ++j) x_prev[j] = a[j];
    };

    // ---- stage 0: prologue row, first erosion row, two full rows ----
    cpwait();
    __syncthreads();
    issue(NSTG - 1);                                       // stage 3
    {
        // t=0: rowmin of row max(r0-1,0) (reflect at top)
        const float* row = smem[0];
        {
            float4 v0 = *(const float4*)(row + c);
            float4 v1 = *(const float4*)(row + c + 4);
            float a[8] = {v0.x, v0.y, v0.z, v0.w, v1.x, v1.y, v1.z, v1.w};
            float xm1 = row[cL], x8r = row[cR];
            rm_prev[0] = fminf(xm1, a[0]);
            #pragma unroll
            for (int j = 1; j < 8; ++j) rm_prev[j] = fminf(a[j - 1], a[j]);
            rm_prev[8] = fminf(a[7], x8r);
        }
        // t=1: erosion row r0 (no output)
        row = smem[1];
        {
            float4 v0 = *(const float4*)(row + c);
            float4 v1 = *(const float4*)(row + c + 4);
            float a[8] = {v0.x, v0.y, v0.z, v0.w, v1.x, v1.y, v1.z, v1.w};
            float xm1 = row[cL], x8r = row[cR];
            float rm[9];
            rm[0] = fminf(xm1, a[0]);
            #pragma unroll
            for (int j = 1; j < 8; ++j) rm[j] = fminf(a[j - 1], a[j]);
            rm[8] = fminf(a[7], x8r);
            #pragma unroll
            for (int j = 0; j < 9; ++j) { er_prev[j] = fminf(rm_prev[j], rm[j]); rm_prev[j] = rm[j]; }
            #pragma unroll
            for (int j = 0; j < 8; ++j) x_prev[j] = a[j];
        }
        full_row(smem[2]);                                 // t=2
        full_row(smem[3]);                                 // t=3
    }

    // ---- steady stages 1..8 ----
    for (int s = 1; s < TSTAGES; ++s) {
        cpwait();
        __syncthreads();
        if (s + NSTG - 1 < TSTAGES) issue(s + NSTG - 1); else cpcommit();
        const int sb = (s % NSTG) * SROWS;
        #pragma unroll
        for (int k = 0; k < SROWS; ++k) {
            const int t = s * SROWS + k;
            if (t <= t_stop) full_row(smem[sb + k]);
        }
    }

    // ---- bottom band: emit row H-1 (dilation clamps row 512 -> 511) ----
    if (bottom) {
        #pragma unroll
        for (int j = 0; j < 8; ++j) {
            float op = fmaxf(er_prev[j], er_prev[j + 1]);
            float d  = x_prev[j] - op;
            acc += d * d;
        }
    }

    // ---- block reduction (reuse smem ring as scratch) ----
    #pragma unroll
    for (int o = 16; o > 0; o >>= 1)
        acc += __shfl_xor_sync(0xffffffffu, acc, o);

    __syncthreads();                                       // everyone done reading ring
    float* sm = &smem[0][0];
    if (lane == 0) sm[wid] = acc;
    __syncthreads();
    if (tid == 0) {
        float t = sm[0] + sm[1];
        g_partials[blockIdx.x] = t;
        __threadfence();
        unsigned int old = atomicAdd(&g_counter, 1u);
        sm[4] = (old == NBLOCKS - 1) ? 1.f : 0.f;
    }
    __syncthreads();

    // ---- last block: deterministic fixed-order final reduction ----
    if (sm[4] != 0.f) {
        const float4* gp4 = (const float4*)g_partials;
        float a = 0.f;
        #pragma unroll
        for (int i = 0; i < NBLOCKS / 4 / NTHR; ++i) {     // 8 iters
            float4 v = gp4[tid + i * NTHR];
            a += (v.x + v.y) + (v.z + v.w);
        }
        #pragma unroll
        for (int o = 16; o > 0; o >>= 1)
            a += __shfl_xor_sync(0xffffffffu, a, o);
        __syncthreads();
        if (lane == 0) sm[8 + wid] = a;
        __syncthreads();
        if (tid == 0) {
            out[0] = (sm[8] + sm[9]) * INV_N;
            g_counter = 0;                                 // self-reset for graph replay
        }
    }
}

extern "C" void kernel_launch(void* const* d_in, const int* in_sizes, int n_in,
                              void* d_out, int out_size) {
    (void)in_sizes; (void)n_in; (void)out_size;
    const float* labels = (const float*)d_in[0];
    float* out = (float*)d_out;
    open_mse_kernel<<<NBLOCKS, NTHR>>>(labels, out);
}